// round 6
// baseline (speedup 1.0000x reference)
#include <cuda_runtime.h>
#include <cuda_bf16.h>
#include <cstdint>

// SoftEmbeddedDecisionRules: balanced binary hierarchy over C=1024 classes.
// One row per warp; per-lane-contiguous compute layout (MUFU-minimal).
// Global<->smem via 1D bulk-async copies (32KB per block, no tensor map).
// Smem linear; bank conflicts avoided by rotated chunk order per lane.
// mbarrier wait: sleep-form try_wait, executed by warp 0 only; other warps
// released via __syncthreads (cheapest wakeup path).

#define BATCH_N 32768
#define NCLASS 1024
#define WARPS_PER_BLOCK 8
#define TILE_BYTES (WARPS_PER_BLOCK * NCLASS * 4)   // 32768 B per block

__device__ __forceinline__ float sigmoidf_fast(float x) {
    return __fdividef(1.0f, 1.0f + __expf(-x));
}

__device__ __forceinline__ void mbar_wait_parity(uint32_t mbar_s, uint32_t parity) {
    asm volatile(
        "{\n\t"
        ".reg .pred P1;\n\t"
        "WAIT_LOOP_%=:\n\t"
        "mbarrier.try_wait.parity.acquire.cta.shared::cta.b64 P1, [%0], %1, 0x989680;\n\t"
        "@P1 bra.uni WAIT_DONE_%=;\n\t"
        "bra.uni WAIT_LOOP_%=;\n\t"
        "WAIT_DONE_%=:\n\t"
        "}"
        :: "r"(mbar_s), "r"(parity) : "memory");
}

__global__ void __launch_bounds__(WARPS_PER_BLOCK * 32)
soft_tree_kernel(const float* __restrict__ in, float* __restrict__ out) {
    __shared__ alignas(128) float4 buf[TILE_BYTES / 16];   // 2048 float4 = 32KB
    __shared__ alignas(8) unsigned long long mbar;

    const int tid  = threadIdx.x;
    const int wib  = tid >> 5;
    const int lane = tid & 31;

    const uint32_t buf_s  = (uint32_t)__cvta_generic_to_shared(buf);
    const uint32_t mbar_s = (uint32_t)__cvta_generic_to_shared(&mbar);

    if (tid == 0) {
        asm volatile("mbarrier.init.shared.b64 [%0], %1;"
                     :: "r"(mbar_s), "r"(1) : "memory");
        asm volatile("fence.proxy.async.shared::cta;" ::: "memory");
        asm volatile("mbarrier.arrive.expect_tx.shared.b64 _, [%0], %1;"
                     :: "r"(mbar_s), "r"((uint32_t)TILE_BYTES) : "memory");
        const float* src = in + (size_t)blockIdx.x * (TILE_BYTES / 4);
        asm volatile(
            "cp.async.bulk.shared::cta.global.mbarrier::complete_tx::bytes "
            "[%0], [%1], %2, [%3];"
            :: "r"(buf_s), "l"(src), "r"((uint32_t)TILE_BYTES), "r"(mbar_s)
            : "memory");
    }
    // Warp 0 waits on the mbarrier (HW-sleep); everyone else blocks on the
    // bar.sync which warp 0 reaches only after the data has landed.
    if (wib == 0) {
        mbar_wait_parity(mbar_s, 0);
    }
    __syncthreads();

    // ---- phase A: read this lane's 32 contiguous classes (rotated order,
    //      conflict-free) and compute s2 sums + leaf sigmoids eagerly ----
    const int segbase = (wib * 32 + lane) * 8;   // lane's 128B segment
    float s2[16], a1[16];
#pragma unroll
    for (int t = 0; t < 8; t++) {
        int i = (t + lane) & 7;                  // rotation kills bank conflicts
        float4 q = buf[segbase + i];
        s2[2 * i + 0] = q.x + q.y;
        a1[2 * i + 0] = sigmoidf_fast(q.x - q.y);
        s2[2 * i + 1] = q.z + q.w;
        a1[2 * i + 1] = sigmoidf_fast(q.z - q.w);
    }

    // ---- upsweep with eager sigmoids ----
    float s4[8], a2[8];
#pragma unroll
    for (int i = 0; i < 8; i++) {
        s4[i] = s2[2 * i] + s2[2 * i + 1];
        a2[i] = sigmoidf_fast((s2[2 * i] - s2[2 * i + 1]) * 0.5f);
    }
    float s8[4], a4[4];
#pragma unroll
    for (int i = 0; i < 4; i++) {
        s8[i] = s4[2 * i] + s4[2 * i + 1];
        a4[i] = sigmoidf_fast((s4[2 * i] - s4[2 * i + 1]) * 0.25f);
    }
    float s16[2], a8[2];
#pragma unroll
    for (int i = 0; i < 2; i++) {
        s16[i] = s8[2 * i] + s8[2 * i + 1];
        a8[i] = sigmoidf_fast((s8[2 * i] - s8[2 * i + 1]) * 0.125f);
    }
    float S   = s16[0] + s16[1];
    float a16 = sigmoidf_fast((s16[0] - s16[1]) * 0.0625f);

    // ---- cross-lane levels: seg = 32, 64, 128, 256, 512 ----
    float F = 1.0f;
    {
        float o;
        o = __shfl_xor_sync(0xffffffffu, S, 1);
        F *= sigmoidf_fast((S - o) * (1.0f / 32.0f));  S += o;
        o = __shfl_xor_sync(0xffffffffu, S, 2);
        F *= sigmoidf_fast((S - o) * (1.0f / 64.0f));  S += o;
        o = __shfl_xor_sync(0xffffffffu, S, 4);
        F *= sigmoidf_fast((S - o) * (1.0f / 128.0f)); S += o;
        o = __shfl_xor_sync(0xffffffffu, S, 8);
        F *= sigmoidf_fast((S - o) * (1.0f / 256.0f)); S += o;
        o = __shfl_xor_sync(0xffffffffu, S, 16);
        F *= sigmoidf_fast((S - o) * (1.0f / 512.0f));
    }

    // ---- downsweep: multiply sigmoid factors top-down ----
    float p16[2];
    p16[0] = F * a16;
    p16[1] = F - p16[0];

    float p8[4];
#pragma unroll
    for (int i = 0; i < 2; i++) {
        p8[2 * i]     = p16[i] * a8[i];
        p8[2 * i + 1] = p16[i] - p8[2 * i];
    }
    float p4[8];
#pragma unroll
    for (int i = 0; i < 4; i++) {
        p4[2 * i]     = p8[i] * a4[i];
        p4[2 * i + 1] = p8[i] - p4[2 * i];
    }
    float p2[16];
#pragma unroll
    for (int i = 0; i < 8; i++) {
        p2[2 * i]     = p4[i] * a2[i];
        p2[2 * i + 1] = p4[i] - p2[2 * i];
    }

    // ---- leaves -> smem in place (own segment only; rotated, conflict-free) ----
#pragma unroll
    for (int t = 0; t < 8; t++) {
        int i = (t + lane) & 7;
        float4 w;
        w.x = p2[2 * i] * a1[2 * i];
        w.y = p2[2 * i] - w.x;
        w.z = p2[2 * i + 1] * a1[2 * i + 1];
        w.w = p2[2 * i + 1] - w.z;
        buf[segbase + i] = w;
    }

    __syncthreads();

    // ---- bulk store smem -> global ----
    if (tid == 0) {
        asm volatile("fence.proxy.async.shared::cta;" ::: "memory");
        float* dst = out + (size_t)blockIdx.x * (TILE_BYTES / 4);
        asm volatile(
            "cp.async.bulk.global.shared::cta.bulk_group [%0], [%1], %2;"
            :: "l"(dst), "r"(buf_s), "r"((uint32_t)TILE_BYTES) : "memory");
        asm volatile("cp.async.bulk.commit_group;" ::: "memory");
        asm volatile("cp.async.bulk.wait_group 0;" ::: "memory");
    }
}

extern "C" void kernel_launch(void* const* d_in, const int* in_sizes, int n_in,
                              void* d_out, int out_size) {
    (void)in_sizes; (void)n_in; (void)out_size;
    const float* in = (const float*)d_in[0];
    float* out = (float*)d_out;
    soft_tree_kernel<<<BATCH_N / WARPS_PER_BLOCK, WARPS_PER_BLOCK * 32>>>(in, out);
}

// round 10
// speedup vs baseline: 3.7961x; 3.7961x over previous
#include <cuda_runtime.h>
#include <cuda_bf16.h>

// SoftEmbeddedDecisionRules: balanced binary hierarchy over C=1024 classes.
// Zero-smem design: one row per warp; lane L owns 8 contiguous classes per
// 256-span: [256j + 8L, 256j+8L+8), j=0..3, loaded as two adjacent float4.
// Levels seg 1/2/4 lane-local; seg 8..128 via shfl butterfly on 8-sums
// (each lane's sigmoid is its own branch factor, no broadcast); seg 256/512
// lane-uniform on the four 256-span sums. No shared memory, no barriers.

#define BATCH_N 32768
#define NCLASS 1024

__device__ __forceinline__ float sigmoidf_fast(float x) {
    return __fdividef(1.0f, 1.0f + __expf(-x));
}

__global__ void __launch_bounds__(256)
soft_tree_kernel(const float* __restrict__ in, float* __restrict__ out) {
    const int warp = (blockIdx.x * blockDim.x + threadIdx.x) >> 5;
    const int lane = threadIdx.x & 31;

    const float4* gin  = reinterpret_cast<const float4*>(in  + (size_t)warp * NCLASS);
    float4*       gout = reinterpret_cast<float4*>(out + (size_t)warp * NCLASS);

    float fl[16];   // leaf factors (4 per 256-span)
    float a2h[8];   // seg=2 factors (2 per span)
    float a4h[4];   // seg=4 factors (1 per span)
    float Bf[4];    // butterfly product seg 8..128 (per span, per lane)
    float Rs[4];    // 256-span sums (lane-uniform)

#pragma unroll
    for (int j = 0; j < 4; j++) {
        float4 qa = gin[j * 64 + 2 * lane];
        float4 qb = gin[j * 64 + 2 * lane + 1];

        // seg=1 (leaves)
        fl[4 * j + 0] = sigmoidf_fast(qa.x - qa.y);
        fl[4 * j + 1] = sigmoidf_fast(qa.z - qa.w);
        fl[4 * j + 2] = sigmoidf_fast(qb.x - qb.y);
        fl[4 * j + 3] = sigmoidf_fast(qb.z - qb.w);

        // seg=2
        float t0 = qa.x + qa.y, t1 = qa.z + qa.w;
        float t2 = qb.x + qb.y, t3 = qb.z + qb.w;
        a2h[2 * j + 0] = sigmoidf_fast((t0 - t1) * 0.5f);
        a2h[2 * j + 1] = sigmoidf_fast((t2 - t3) * 0.5f);

        // seg=4
        float u0 = t0 + t1, u1 = t2 + t3;
        a4h[j] = sigmoidf_fast((u0 - u1) * 0.25f);

        // seg=8..128 butterfly on the lane's 8-sum
        float Q = u0 + u1;
        float Bacc, o;
        o = __shfl_xor_sync(0xffffffffu, Q, 1);
        Bacc = sigmoidf_fast((Q - o) * (1.0f / 8.0f));    Q += o;
        o = __shfl_xor_sync(0xffffffffu, Q, 2);
        Bacc *= sigmoidf_fast((Q - o) * (1.0f / 16.0f));  Q += o;
        o = __shfl_xor_sync(0xffffffffu, Q, 4);
        Bacc *= sigmoidf_fast((Q - o) * (1.0f / 32.0f));  Q += o;
        o = __shfl_xor_sync(0xffffffffu, Q, 8);
        Bacc *= sigmoidf_fast((Q - o) * (1.0f / 64.0f));  Q += o;
        o = __shfl_xor_sync(0xffffffffu, Q, 16);
        Bacc *= sigmoidf_fast((Q - o) * (1.0f / 128.0f)); Q += o;
        Bf[j] = Bacc;
        Rs[j] = Q;   // full 256-span sum, uniform across lanes
    }

    // ---- top levels (lane-uniform): seg=256 and seg=512 ----
    float c0 = sigmoidf_fast((Rs[0] - Rs[1]) * (1.0f / 256.0f));
    float c1 = sigmoidf_fast((Rs[2] - Rs[3]) * (1.0f / 256.0f));
    float W0 = Rs[0] + Rs[1], W1 = Rs[2] + Rs[3];
    float d  = sigmoidf_fast((W0 - W1) * (1.0f / 512.0f));

    float T[4];
    T[0] = d * c0;
    T[1] = d - T[0];
    float e = 1.0f - d;
    T[2] = e * c1;
    T[3] = e - T[2];

    // ---- downsweep + store (same addressing as loads: fully streamed) ----
#pragma unroll
    for (int j = 0; j < 4; j++) {
        float base = T[j] * Bf[j];
        float P0 = base * a4h[j];
        float P1 = base - P0;
        float q0 = P0 * a2h[2 * j];     float q1 = P0 - q0;
        float q2 = P1 * a2h[2 * j + 1]; float q3 = P1 - q2;

        float4 w0, w1;
        w0.x = q0 * fl[4 * j + 0]; w0.y = q0 - w0.x;
        w0.z = q1 * fl[4 * j + 1]; w0.w = q1 - w0.z;
        w1.x = q2 * fl[4 * j + 2]; w1.y = q2 - w1.x;
        w1.z = q3 * fl[4 * j + 3]; w1.w = q3 - w1.z;

        gout[j * 64 + 2 * lane]     = w0;
        gout[j * 64 + 2 * lane + 1] = w1;
    }
}

extern "C" void kernel_launch(void* const* d_in, const int* in_sizes, int n_in,
                              void* d_out, int out_size) {
    (void)in_sizes; (void)n_in; (void)out_size;
    const float* in = (const float*)d_in[0];
    float* out = (float*)d_out;
    // 32768 rows, 1 row per warp, 8 warps per block -> 4096 blocks
    soft_tree_kernel<<<BATCH_N / 8, 256>>>(in, out);
}